// round 1
// baseline (speedup 1.0000x reference)
#include <cuda_runtime.h>
#include <cuda_bf16.h>

#define SS   8
#define HH   544
#define WW   960
#define HID  64

__global__ __launch_bounds__(256)
void sky_kernel(const float* __restrict__ images,
                const float* __restrict__ extr,
                const float* __restrict__ intr,
                const float* __restrict__ W1,
                const float* __restrict__ b1,
                const float* __restrict__ W2,
                const float* __restrict__ b2,
                const float* __restrict__ pcd,
                const float* __restrict__ lsc,
                const int*   __restrict__ dsp,
                float* __restrict__ out, int N)
{
    __shared__ float sE[SS * 12];    // extrinsics rows 0..2 (3x4 each)
    __shared__ float sK[SS * 9];     // Ks = intrinsics / D
    __shared__ float sW1[3 * HID];   // (3,64) row-major
    __shared__ float sB1[HID];
    __shared__ float sW2[HID * 3];   // only first 3 output cols are used (rgb)
    __shared__ float sB2[3];

    const int tid = threadIdx.x;

    // decode downsample whether stored as int32 or float32 bits
    float ds;
    {
        int iv = *dsp;
        ds = (iv > 0 && iv < 1000000) ? (float)iv : __int_as_float(iv);
    }

    if (tid < SS * 12) sE[tid] = extr[(tid / 12) * 16 + (tid % 12)];
    if (tid < SS * 9) {
        int ij = tid % 9, i = ij / 3, j = ij % 3;
        float d = 1.0f;
        if (i == 0 && (j == 0 || j == 2)) d = ds;
        if (i == 1 && (j == 1 || j == 2)) d = ds;
        sK[tid] = intr[tid] / d;
    }
    if (tid < 3 * HID) sW1[tid] = W1[tid];
    if (tid < HID)     sB1[tid] = b1[tid];
    if (tid < HID * 3) sW2[tid] = W2[(tid / 3) * 6 + (tid % 3)];
    if (tid < 3)       sB2[tid] = b2[tid];
    __syncthreads();

    const int n = blockIdx.x * blockDim.x + tid;
    if (n >= N) return;

    const float X = pcd[3 * n + 0];
    const float Y = pcd[3 * n + 1];
    const float Z = pcd[3 * n + 2];

    float f0 = 0.f, f1 = 0.f, f2 = 0.f, cnt = 0.f;
    bool any = false;

    #pragma unroll
    for (int s = 0; s < SS; ++s) {
        const float* E = sE + s * 12;
        const float* K = sK + s * 9;
        // cam = E[:3,:4] @ [X,Y,Z,1]   (same op order as reference)
        float c0 = E[0] * X + E[1]  * Y + E[2]  * Z + E[3];
        float c1 = E[4] * X + E[5]  * Y + E[6]  * Z + E[7];
        float c2 = E[8] * X + E[9]  * Y + E[10] * Z + E[11];
        // uv = Ks @ cam  (full 3x3 as reference does)
        float u = K[0] * c0 + K[1] * c1 + K[2] * c2;
        float v = K[3] * c0 + K[4] * c1 + K[5] * c2;
        float w = K[6] * c0 + K[7] * c1 + K[8] * c2;
        float zs = (fabsf(w) > 1e-6f) ? w : 1e-6f;
        float px = u / zs;
        float py = v / zs;
        bool m = (w > 0.001f) && (px >= 0.f) && (px <= (float)(WW - 1)) &&
                 (py >= 0.f) && (py <= (float)(HH - 1));
        if (m) {
            int x0 = (int)floorf(px); x0 = min(max(x0, 0), WW - 2);
            int y0 = (int)floorf(py); y0 = min(max(y0, 0), HH - 2);
            float wx = px - (float)x0;
            float wy = py - (float)y0;
            float w00 = (1.f - wx) * (1.f - wy);
            float w01 = wx * (1.f - wy);
            float w10 = (1.f - wx) * wy;
            float w11 = wx * wy;
            const float* img = images + (size_t)s * 3 * HH * WW + (size_t)y0 * WW + x0;
            {
                const float* p = img;
                f0 += p[0] * w00 + p[1] * w01 + p[WW] * w10 + p[WW + 1] * w11;
            }
            {
                const float* p = img + (size_t)HH * WW;
                f1 += p[0] * w00 + p[1] * w01 + p[WW] * w10 + p[WW + 1] * w11;
            }
            {
                const float* p = img + (size_t)2 * HH * WW;
                f2 += p[0] * w00 + p[1] * w01 + p[WW] * w10 + p[WW + 1] * w11;
            }
            cnt += 1.f;
            any = true;
        }
    }

    const float inv = 1.f / fmaxf(cnt, 1.f);
    f0 *= inv; f1 *= inv; f2 *= inv;

    // MLP: h = relu(feat @ W1 + b1); rgb = tanh(h @ W2[:, :3] + b2[:3])
    float a0 = sB2[0], a1 = sB2[1], a2 = sB2[2];
    #pragma unroll
    for (int j = 0; j < HID; ++j) {
        float h = f0 * sW1[j] + f1 * sW1[HID + j] + f2 * sW1[2 * HID + j] + sB1[j];
        h = fmaxf(h, 0.f);
        a0 = fmaf(h, sW2[j * 3 + 0], a0);
        a1 = fmaf(h, sW2[j * 3 + 1], a1);
        a2 = fmaf(h, sW2[j * 3 + 2], a2);
    }

    const float pm = any ? 1.f : 0.f;
    float* op = out + (size_t)6 * n;
    op[0] = tanhf(a0) * pm;
    op[1] = tanhf(a1) * pm;
    op[2] = tanhf(a2) * pm;
    op[3] = expf(lsc[3 * n + 0]) * pm;
    op[4] = expf(lsc[3 * n + 1]) * pm;
    op[5] = expf(lsc[3 * n + 2]) * pm;
}

extern "C" void kernel_launch(void* const* d_in, const int* in_sizes, int n_in,
                              void* d_out, int out_size)
{
    const float* images = (const float*)d_in[0];
    const float* extr   = (const float*)d_in[1];
    const float* intr   = (const float*)d_in[2];
    const float* W1     = (const float*)d_in[3];
    const float* b1     = (const float*)d_in[4];
    const float* W2     = (const float*)d_in[5];
    const float* b2     = (const float*)d_in[6];
    const float* pcd    = (const float*)d_in[7];
    const float* lsc    = (const float*)d_in[8];
    const int*   dsp    = (const int*)  d_in[9];

    int N = in_sizes[7] / 3;
    int threads = 256;
    int blocks = (N + threads - 1) / threads;
    sky_kernel<<<blocks, threads>>>(images, extr, intr, W1, b1, W2, b2,
                                    pcd, lsc, dsp, (float*)d_out, N);
}